// round 9
// baseline (speedup 1.0000x reference)
#include <cuda_runtime.h>
#include <math.h>
#include <stdint.h>

// ---------------------------------------------------------------------------
// SimpleTransformerLayer on GB300 — Round 9
//   3-stage cp.async pipelines (2 tiles of compute cover per load).
//   CVT-free tf32 mma mainloops (rounding hoisted to producers).
// ---------------------------------------------------------------------------

#define BATCH   2
#define SEQ     2048
#define DIM     1024
#define HEADS   16
#define DHEAD   64
#define INNER   1024
#define FFDIM   4096
#define ROWS    (BATCH * SEQ)
#define LN_EPS  1e-5f

__device__ float g_h   [ROWS * DIM];          // LN output (tf32-rounded)
__device__ float g_qkv [ROWS * 3 * INNER];    // QKV (tf32-rounded)
__device__ float g_attn[ROWS * INNER];        // attention out (tf32-rounded)
__device__ float g_x1  [ROWS * DIM];          // residual stream (fp32)
__device__ float g_ff  [ROWS * FFDIM];        // GELU out (tf32-rounded)
__device__ float g_wqkv[DIM * 3 * INNER];     // tf32-rounded weights
__device__ float g_wout[INNER * DIM];
__device__ float g_wff1[DIM * FFDIM];
__device__ float g_wff2[FFDIM * DIM];

// --------------------------- async-copy helpers -----------------------------
__device__ __forceinline__ void cp16(uint32_t smem, const void* gmem) {
    asm volatile("cp.async.cg.shared.global [%0], [%1], 16;\n"
                 :: "r"(smem), "l"(gmem));
}
__device__ __forceinline__ void cp_commit() {
    asm volatile("cp.async.commit_group;\n" ::);
}
template<int N> __device__ __forceinline__ void cp_wait() {
    asm volatile("cp.async.wait_group %0;\n" :: "n"(N));
}
__device__ __forceinline__ uint32_t smem_u32(const void* p) {
    return (uint32_t)__cvta_generic_to_shared(p);
}

// --------------------------- mma helpers ------------------------------------
__device__ __forceinline__ uint32_t f2tf32(float f) {
    uint32_t r;
    asm("cvt.rna.tf32.f32 %0, %1;\n" : "=r"(r) : "f"(f));
    return r;
}
__device__ __forceinline__ float round_tf32(float f) {
    return __uint_as_float(f2tf32(f));
}
__device__ __forceinline__ void mma_tf32(
    float& c0, float& c1, float& c2, float& c3,
    uint32_t a0, uint32_t a1, uint32_t a2, uint32_t a3,
    uint32_t b0, uint32_t b1)
{
    asm volatile(
        "mma.sync.aligned.m16n8k8.row.col.f32.tf32.tf32.f32 "
        "{%0,%1,%2,%3}, {%4,%5,%6,%7}, {%8,%9}, {%0,%1,%2,%3};\n"
        : "+f"(c0), "+f"(c1), "+f"(c2), "+f"(c3)
        : "r"(a0), "r"(a1), "r"(a2), "r"(a3), "r"(b0), "r"(b1));
}

// -------------------- weight pre-rounding (once per launch) -----------------
__global__ __launch_bounds__(256) void round_tf32_kernel(
    const float* __restrict__ in, float* __restrict__ out, int n4)
{
    const int i = blockIdx.x * blockDim.x + threadIdx.x;
    if (i < n4) {
        float4 v = reinterpret_cast<const float4*>(in)[i];
        v.x = round_tf32(v.x); v.y = round_tf32(v.y);
        v.z = round_tf32(v.z); v.w = round_tf32(v.w);
        reinterpret_cast<float4*>(out)[i] = v;
    }
}

// ------------------------------ LayerNorm ----------------------------------
__global__ __launch_bounds__(256) void layernorm_kernel(
    const float* __restrict__ x, const float* __restrict__ g,
    const float* __restrict__ b, float* __restrict__ y)
{
    __shared__ float red[2][8];
    const int row = blockIdx.x;
    const int tid = threadIdx.x;
    const float4* xr = reinterpret_cast<const float4*>(x + (size_t)row * DIM);
    float4 v = xr[tid];
    float s  = v.x + v.y + v.z + v.w;
    float ss = v.x * v.x + v.y * v.y + v.z * v.z + v.w * v.w;
    #pragma unroll
    for (int o = 16; o > 0; o >>= 1) {
        s  += __shfl_down_sync(0xffffffffu, s,  o);
        ss += __shfl_down_sync(0xffffffffu, ss, o);
    }
    if ((tid & 31) == 0) { red[0][tid >> 5] = s; red[1][tid >> 5] = ss; }
    __syncthreads();
    if (tid < 32) {
        s  = (tid < 8) ? red[0][tid] : 0.f;
        ss = (tid < 8) ? red[1][tid] : 0.f;
        #pragma unroll
        for (int o = 4; o > 0; o >>= 1) {
            s  += __shfl_down_sync(0xffffffffu, s,  o);
            ss += __shfl_down_sync(0xffffffffu, ss, o);
        }
        if (tid == 0) { red[0][0] = s; red[1][0] = ss; }
    }
    __syncthreads();
    const float mu  = red[0][0] * (1.f / DIM);
    const float var = red[1][0] * (1.f / DIM) - mu * mu;
    const float inv = rsqrtf(var + LN_EPS);
    const float4 gg = reinterpret_cast<const float4*>(g)[tid];
    const float4 bb = reinterpret_cast<const float4*>(b)[tid];
    float4 o;
    o.x = round_tf32((v.x - mu) * inv * gg.x + bb.x);
    o.y = round_tf32((v.y - mu) * inv * gg.y + bb.y);
    o.z = round_tf32((v.z - mu) * inv * gg.z + bb.z);
    o.w = round_tf32((v.w - mu) * inv * gg.w + bb.w);
    reinterpret_cast<float4*>(y + (size_t)row * DIM)[tid] = o;
}

// --------------------------- tf32 tensor GEMM -------------------------------
// Inputs A,B already tf32-rounded. CTA 128x128xBK32, 8 warps, 64x32/warp.
// 3-stage cp.async: at iter k, stages hold tiles k, k+1, and (being filled)
// k+2. cp_wait<1> completes tile k while tile k+1 stays in flight.
#define E_ROUND     0
#define E_BIAS_GELU 1
#define E_BIAS_RES  2

#define GBK 32
#define ALD 36
#define BLD 136
#define ASZ (128 * ALD)
#define BSZ (GBK * BLD)
#define GSTAGES 3
#define GEMM_SMEM_BYTES ((GSTAGES * (ASZ + BSZ)) * (int)sizeof(float))

template<int EPI>
__global__ __launch_bounds__(256) void gemm_tc_kernel(
    const float* __restrict__ A, const float* __restrict__ B,
    const float* __restrict__ bias, const float* __restrict__ res,
    float* __restrict__ C, int M, int N, int K)
{
    constexpr int BM = 128, BN = 128;
    extern __shared__ float smem_dyn[];
    float* As = smem_dyn;                       // GSTAGES x ASZ
    float* Bs = smem_dyn + GSTAGES * ASZ;       // GSTAGES x BSZ

    const int tid   = threadIdx.x;
    const int warp  = tid >> 5;
    const int lane  = tid & 31;
    const int warpM = warp >> 2;
    const int warpN = warp & 3;
    const int g8    = lane >> 2;
    const int tig   = lane & 3;

    const float* Ab = A + (size_t)blockIdx.y * BM * K;
    const float* Bb = B + (size_t)blockIdx.x * BN;

    float acc[4][4][4];
    #pragma unroll
    for (int mi = 0; mi < 4; mi++)
        #pragma unroll
        for (int ni = 0; ni < 4; ni++)
            #pragma unroll
            for (int q = 0; q < 4; q++) acc[mi][ni][q] = 0.f;

    auto issueTile = [&](int kt, int s) {
        float* As_ = As + s * ASZ;
        float* Bs_ = Bs + s * BSZ;
        #pragma unroll
        for (int i = 0; i < 4; i++) {
            int idx = tid + i * 256;
            int r = idx >> 3, c4 = idx & 7;
            cp16(smem_u32(As_ + r * ALD + c4 * 4),
                 Ab + (size_t)r * K + kt * GBK + c4 * 4);
        }
        #pragma unroll
        for (int i = 0; i < 4; i++) {
            int idx = tid + i * 256;
            int r = idx >> 5, c4 = idx & 31;
            cp16(smem_u32(Bs_ + r * BLD + c4 * 4),
                 Bb + (size_t)(kt * GBK + r) * N + c4 * 4);
        }
        cp_commit();
    };

    const int nk = K / GBK;
    issueTile(0, 0);
    if (nk > 1) issueTile(1, 1);

    for (int kt = 0; kt < nk; kt++) {
        const int cur = kt % GSTAGES;
        if (kt + 1 < nk) cp_wait<1>(); else cp_wait<0>();
        __syncthreads();
        if (kt + 2 < nk) issueTile(kt + 2, (kt + 2) % GSTAGES);

        const float* As_ = As + cur * ASZ;
        const float* Bs_ = Bs + cur * BSZ;

        #pragma unroll
        for (int kk = 0; kk < 4; kk++) {
            const int k0 = kk * 8 + tig;
            uint32_t Af[4][4], Bf[4][2];
            #pragma unroll
            for (int mi = 0; mi < 4; mi++) {
                const int row0 = warpM * 64 + mi * 16 + g8;
                Af[mi][0] = __float_as_uint(As_[row0 * ALD + k0]);
                Af[mi][1] = __float_as_uint(As_[(row0 + 8) * ALD + k0]);
                Af[mi][2] = __float_as_uint(As_[row0 * ALD + k0 + 4]);
                Af[mi][3] = __float_as_uint(As_[(row0 + 8) * ALD + k0 + 4]);
            }
            #pragma unroll
            for (int ni = 0; ni < 4; ni++) {
                const int col = warpN * 32 + ni * 8 + g8;
                Bf[ni][0] = __float_as_uint(Bs_[k0 * BLD + col]);
                Bf[ni][1] = __float_as_uint(Bs_[(k0 + 4) * BLD + col]);
            }
            #pragma unroll
            for (int mi = 0; mi < 4; mi++)
                #pragma unroll
                for (int ni = 0; ni < 4; ni++)
                    mma_tf32(acc[mi][ni][0], acc[mi][ni][1],
                             acc[mi][ni][2], acc[mi][ni][3],
                             Af[mi][0], Af[mi][1], Af[mi][2], Af[mi][3],
                             Bf[ni][0], Bf[ni][1]);
        }
    }

    // ------------------------------ epilogue --------------------------------
    const int rbase = blockIdx.y * BM + warpM * 64;
    const int cbase = blockIdx.x * BN + warpN * 32;
    #pragma unroll
    for (int mi = 0; mi < 4; mi++) {
        #pragma unroll
        for (int ni = 0; ni < 4; ni++) {
            const int col0 = cbase + ni * 8 + tig * 2;
            #pragma unroll
            for (int half = 0; half < 2; half++) {
                const int row = rbase + mi * 16 + g8 + half * 8;
                float v0 = acc[mi][ni][half * 2 + 0];
                float v1 = acc[mi][ni][half * 2 + 1];
                if (EPI == E_ROUND) {
                    v0 = round_tf32(v0);
                    v1 = round_tf32(v1);
                } else if (EPI == E_BIAS_GELU) {
                    v0 += bias[col0];
                    v1 += bias[col0 + 1];
                    v0 = round_tf32(0.5f * v0 * (1.0f + erff(v0 * 0.70710678118654752f)));
                    v1 = round_tf32(0.5f * v1 * (1.0f + erff(v1 * 0.70710678118654752f)));
                } else if (EPI == E_BIAS_RES) {
                    const float2 rr = *reinterpret_cast<const float2*>(
                        res + (size_t)row * N + col0);
                    v0 += bias[col0]     + rr.x;
                    v1 += bias[col0 + 1] + rr.y;
                }
                *reinterpret_cast<float2*>(C + (size_t)row * N + col0) =
                    make_float2(v0, v1);
            }
        }
    }
}

// ----------------------- tensor-core flash attention ------------------------
// 3-stage cp.async K/V pipeline; qkv tf32-rounded at source; P rounded at store.
#define KLD 68
#define VLD 72
#define PLD 36
#define KSZ (32 * KLD)
#define VSZ (32 * VLD)
#define ASTAGES 3
#define ATTN_SMEM_BYTES ((ASTAGES * (KSZ + VSZ) + 128 * PLD) * (int)sizeof(float))

__global__ __launch_bounds__(128, 2) void flash_attn_tc_kernel(
    const float* __restrict__ qkv, float* __restrict__ out)
{
    constexpr int TK = 32, LD = 3 * INNER;
    extern __shared__ float smem_dyn[];
    float* Ks = smem_dyn;                              // ASTAGES x KSZ
    float* Vs = smem_dyn + ASTAGES * KSZ;              // ASTAGES x VSZ
    float* Ps = smem_dyn + ASTAGES * (KSZ + VSZ);      // 128 x PLD

    const int bh   = blockIdx.y;
    const int b    = bh / HEADS, h = bh % HEADS;
    const int tid  = threadIdx.x;
    const int warp = tid >> 5;
    const int lane = tid & 31;
    const int g8   = lane >> 2;
    const int tig  = lane & 3;

    const float* base = qkv + (size_t)b * SEQ * LD;
    const int wq = blockIdx.x * 128 + warp * 32;

    // preload Q fragments (already tf32-rounded in gmem)
    uint32_t Aq[2][8][4];
    #pragma unroll
    for (int mi = 0; mi < 2; mi++) {
        const int r0 = wq + mi * 16 + g8;
        const float* q0 = base + (size_t)r0 * LD + h * DHEAD;
        const float* q1 = q0 + 8 * LD;
        #pragma unroll
        for (int kk = 0; kk < 8; kk++) {
            Aq[mi][kk][0] = __float_as_uint(q0[kk * 8 + tig]);
            Aq[mi][kk][1] = __float_as_uint(q1[kk * 8 + tig]);
            Aq[mi][kk][2] = __float_as_uint(q0[kk * 8 + tig + 4]);
            Aq[mi][kk][3] = __float_as_uint(q1[kk * 8 + tig + 4]);
        }
    }

    float accO[2][8][4];
    #pragma unroll
    for (int mi = 0; mi < 2; mi++)
        #pragma unroll
        for (int nd = 0; nd < 8; nd++)
            #pragma unroll
            for (int q = 0; q < 4; q++) accO[mi][nd][q] = 0.f;
    float mrow[2][2], lrow[2][2];
    #pragma unroll
    for (int mi = 0; mi < 2; mi++)
        #pragma unroll
        for (int hh = 0; hh < 2; hh++) { mrow[mi][hh] = -INFINITY; lrow[mi][hh] = 0.f; }

    const float scale = 0.125f;
    float* Pw = Ps + warp * 32 * PLD;

    auto issueKV = [&](int kt, int s) {
        float* Ks_ = Ks + s * KSZ;
        float* Vs_ = Vs + s * VSZ;
        #pragma unroll
        for (int i = 0; i < 4; i++) {
            int idx = tid + i * 128;
            int r = idx >> 4, c = idx & 15;
            const int srow = kt * TK + r;
            const float* kp = base + (size_t)srow * LD + INNER     + h * DHEAD + c * 4;
            const float* vp = base + (size_t)srow * LD + 2 * INNER + h * DHEAD + c * 4;
            cp16(smem_u32(Ks_ + r * KLD + c * 4), kp);
            cp16(smem_u32(Vs_ + r * VLD + c * 4), vp);
        }
        cp_commit();
    };

    const int nkt = SEQ / TK;
    issueKV(0, 0);
    issueKV(1, 1);

    for (int kt = 0; kt < nkt; kt++) {
        const int cur = kt % ASTAGES;
        if (kt + 1 < nkt) cp_wait<1>(); else cp_wait<0>();
        __syncthreads();
        if (kt + 2 < nkt) issueKV(kt + 2, (kt + 2) % ASTAGES);

        const float* Ks_ = Ks + cur * KSZ;
        const float* Vs_ = Vs + cur * VSZ;

        // ---- S = Q K^T ----
        float accS[2][4][4];
        #pragma unroll
        for (int mi = 0; mi < 2; mi++)
            #pragma unroll
            for (int ni = 0; ni < 4; ni++)
                #pragma unroll
                for (int q = 0; q < 4; q++) accS[mi][ni][q] = 0.f;

        #pragma unroll
        for (int kk = 0; kk < 8; kk++) {
            uint32_t Bk[4][2];
            #pragma unroll
            for (int ni = 0; ni < 4; ni++) {
                const int key = ni * 8 + g8;
                Bk[ni][0] = __float_as_uint(Ks_[key * KLD + kk * 8 + tig]);
                Bk[ni][1] = __float_as_uint(Ks_[key * KLD + kk * 8 + tig + 4]);
            }
            #pragma unroll
            for (int mi = 0; mi < 2; mi++)
                #pragma unroll
                for (int ni = 0; ni < 4; ni++)
                    mma_tf32(accS[mi][ni][0], accS[mi][ni][1],
                             accS[mi][ni][2], accS[mi][ni][3],
                             Aq[mi][kk][0], Aq[mi][kk][1],
                             Aq[mi][kk][2], Aq[mi][kk][3],
                             Bk[ni][0], Bk[ni][1]);
        }

        // ---- online softmax + P (rounded at store) ----
        #pragma unroll
        for (int mi = 0; mi < 2; mi++) {
            #pragma unroll
            for (int hh = 0; hh < 2; hh++) {
                float v[8];
                #pragma unroll
                for (int ni = 0; ni < 4; ni++) {
                    v[ni * 2 + 0] = accS[mi][ni][hh * 2 + 0] * scale;
                    v[ni * 2 + 1] = accS[mi][ni][hh * 2 + 1] * scale;
                }
                float mx = v[0];
                #pragma unroll
                for (int j = 1; j < 8; j++) mx = fmaxf(mx, v[j]);
                mx = fmaxf(mx, __shfl_xor_sync(0xffffffffu, mx, 1));
                mx = fmaxf(mx, __shfl_xor_sync(0xffffffffu, mx, 2));

                const float mold = mrow[mi][hh];
                const float mnew = fmaxf(mold, mx);
                const float corr = __expf(mold - mnew);
                mrow[mi][hh] = mnew;

                float ps = 0.f;
                #pragma unroll
                for (int j = 0; j < 8; j++) {
                    v[j] = round_tf32(__expf(v[j] - mnew));
                    ps += v[j];
                }
                ps += __shfl_xor_sync(0xffffffffu, ps, 1);
                ps += __shfl_xor_sync(0xffffffffu, ps, 2);
                lrow[mi][hh] = lrow[mi][hh] * corr + ps;

                #pragma unroll
                for (int nd = 0; nd < 8; nd++) {
                    accO[mi][nd][hh * 2 + 0] *= corr;
                    accO[mi][nd][hh * 2 + 1] *= corr;
                }
                const int prow = mi * 16 + g8 + hh * 8;
                #pragma unroll
                for (int ni = 0; ni < 4; ni++)
                    *reinterpret_cast<float2*>(&Pw[prow * PLD + ni * 8 + tig * 2]) =
                        make_float2(v[ni * 2 + 0], v[ni * 2 + 1]);
            }
        }
        __syncwarp();

        // ---- O += P V ----
        #pragma unroll
        for (int kk = 0; kk < 4; kk++) {
            uint32_t Ap[2][4];
            #pragma unroll
            for (int mi = 0; mi < 2; mi++) {
                const int r0 = mi * 16 + g8;
                Ap[mi][0] = __float_as_uint(Pw[r0 * PLD + kk * 8 + tig]);
                Ap[mi][1] = __float_as_uint(Pw[(r0 + 8) * PLD + kk * 8 + tig]);
                Ap[mi][2] = __float_as_uint(Pw[r0 * PLD + kk * 8 + tig + 4]);
                Ap[mi][3] = __float_as_uint(Pw[(r0 + 8) * PLD + kk * 8 + tig + 4]);
            }
            #pragma unroll
            for (int nd = 0; nd < 8; nd++) {
                uint32_t b0 = __float_as_uint(Vs_[(kk * 8 + tig) * VLD + nd * 8 + g8]);
                uint32_t b1 = __float_as_uint(Vs_[(kk * 8 + tig + 4) * VLD + nd * 8 + g8]);
                #pragma unroll
                for (int mi = 0; mi < 2; mi++)
                    mma_tf32(accO[mi][nd][0], accO[mi][nd][1],
                             accO[mi][nd][2], accO[mi][nd][3],
                             Ap[mi][0], Ap[mi][1], Ap[mi][2], Ap[mi][3],
                             b0, b1);
            }
        }
        __syncwarp();
    }

    // ---- normalize + write out (tf32-rounded; consumed as GEMM A) ----
    #pragma unroll
    for (int mi = 0; mi < 2; mi++) {
        #pragma unroll
        for (int hh = 0; hh < 2; hh++) {
            const float inv = 1.f / lrow[mi][hh];
            const int row = wq + mi * 16 + g8 + hh * 8;
            float* op = out + (size_t)(b * SEQ + row) * INNER + h * DHEAD;
            #pragma unroll
            for (int nd = 0; nd < 8; nd++) {
                *reinterpret_cast<float2*>(op + nd * 8 + tig * 2) =
                    make_float2(round_tf32(accO[mi][nd][hh * 2 + 0] * inv),
                                round_tf32(accO[mi][nd][hh * 2 + 1] * inv));
            }
        }
    }
}

// ------------------------------- launch -------------------------------------
extern "C" void kernel_launch(void* const* d_in, const int* in_sizes, int n_in,
                              void* d_out, int out_size)
{
    const float* x     = (const float*)d_in[0];
    const float* w_qkv = (const float*)d_in[1];
    const float* w_out = (const float*)d_in[2];
    const float* b_out = (const float*)d_in[3];
    const float* g1    = (const float*)d_in[4];
    const float* be1   = (const float*)d_in[5];
    const float* g2    = (const float*)d_in[6];
    const float* be2   = (const float*)d_in[7];
    const float* w_ff1 = (const float*)d_in[8];
    const float* b_ff1 = (const float*)d_in[9];
    const float* w_ff2 = (const float*)d_in[10];
    const float* b_ff2 = (const float*)d_in[11];
    float* out = (float*)d_out;

    float *h, *qkv, *attn, *x1, *ff, *wq, *wo, *w1, *w2;
    cudaGetSymbolAddress((void**)&h,    g_h);
    cudaGetSymbolAddress((void**)&qkv,  g_qkv);
    cudaGetSymbolAddress((void**)&attn, g_attn);
    cudaGetSymbolAddress((void**)&x1,   g_x1);
    cudaGetSymbolAddress((void**)&ff,   g_ff);
    cudaGetSymbolAddress((void**)&wq,   g_wqkv);
    cudaGetSymbolAddress((void**)&wo,   g_wout);
    cudaGetSymbolAddress((void**)&w1,   g_wff1);
    cudaGetSymbolAddress((void**)&w2,   g_wff2);

    // Opt-in to >48KB dynamic smem (immediate host-side ops, graph-safe).
    cudaFuncSetAttribute(gemm_tc_kernel<E_ROUND>,
        cudaFuncAttributeMaxDynamicSharedMemorySize, GEMM_SMEM_BYTES);
    cudaFuncSetAttribute(gemm_tc_kernel<E_BIAS_GELU>,
        cudaFuncAttributeMaxDynamicSharedMemorySize, GEMM_SMEM_BYTES);
    cudaFuncSetAttribute(gemm_tc_kernel<E_BIAS_RES>,
        cudaFuncAttributeMaxDynamicSharedMemorySize, GEMM_SMEM_BYTES);
    cudaFuncSetAttribute(flash_attn_tc_kernel,
        cudaFuncAttributeMaxDynamicSharedMemorySize, ATTN_SMEM_BYTES);

    // 0) tf32-round the weights (deterministic pre-pass, ~13us)
    {
        const int n1 = DIM * 3 * INNER / 4, n2 = INNER * DIM / 4;
        const int n3 = DIM * FFDIM / 4,     n4 = FFDIM * DIM / 4;
        round_tf32_kernel<<<(n1 + 255) / 256, 256>>>(w_qkv, wq, n1);
        round_tf32_kernel<<<(n2 + 255) / 256, 256>>>(w_out, wo, n2);
        round_tf32_kernel<<<(n3 + 255) / 256, 256>>>(w_ff1, w1, n3);
        round_tf32_kernel<<<(n4 + 255) / 256, 256>>>(w_ff2, w2, n4);
    }

    layernorm_kernel<<<ROWS, 256>>>(x, g1, be1, h);
    gemm_tc_kernel<E_ROUND><<<dim3(3 * INNER / 128, ROWS / 128), 256,
                              GEMM_SMEM_BYTES>>>(
        h, wq, nullptr, nullptr, qkv, ROWS, 3 * INNER, DIM);
    flash_attn_tc_kernel<<<dim3(SEQ / 128, BATCH * HEADS), 128,
                           ATTN_SMEM_BYTES>>>(qkv, attn);
    gemm_tc_kernel<E_BIAS_RES><<<dim3(DIM / 128, ROWS / 128), 256,
                                 GEMM_SMEM_BYTES>>>(
        attn, wo, b_out, x, x1, ROWS, DIM, INNER);
    layernorm_kernel<<<ROWS, 256>>>(x1, g2, be2, h);
    gemm_tc_kernel<E_BIAS_GELU><<<dim3(FFDIM / 128, ROWS / 128), 256,
                                  GEMM_SMEM_BYTES>>>(
        h, w1, b_ff1, nullptr, ff, ROWS, FFDIM, DIM);
    gemm_tc_kernel<E_BIAS_RES><<<dim3(DIM / 128, ROWS / 128), 256,
                                 GEMM_SMEM_BYTES>>>(
        ff, w2, b_ff2, x1, out, ROWS, DIM, FFDIM);
}

// round 16
// speedup vs baseline: 1.5294x; 1.5294x over previous
#include <cuda_runtime.h>
#include <cuda_fp16.h>
#include <math.h>
#include <stdint.h>

// ---------------------------------------------------------------------------
// SimpleTransformerLayer on GB300 — Round 16 (audited fp16 kernel, resubmit)
//   tcgen05 unavailable (.target sm_103). fp16 mma.sync m16n8k16 (2x tf32
//   rate, same 10-bit mantissa) for all GEMMs + attention S=QK^T;
//   P*V stays tf32/fp32. 3-stage cp.async everywhere.
// ---------------------------------------------------------------------------

#define BATCH   2
#define SEQ     2048
#define DIM     1024
#define HEADS   16
#define DHEAD   64
#define INNER   1024
#define FFDIM   4096
#define ROWS    (BATCH * SEQ)
#define LN_EPS  1e-5f

__device__ __half g_h   [ROWS * DIM];         // LN output (fp16)
__device__ __half g_qk  [ROWS * 2 * INNER];   // Q|K halves of QKV (fp16)
__device__ float  g_v   [ROWS * INNER];       // V part (fp32, tf32-rounded)
__device__ __half g_attn[ROWS * INNER];       // attention out (fp16)
__device__ float  g_x1  [ROWS * DIM];         // residual stream (fp32)
__device__ __half g_ff  [ROWS * FFDIM];       // GELU out (fp16)
// transposed fp16 weights: Wt[N][K]
__device__ __half g_wqkv[3 * INNER * DIM];
__device__ __half g_wout[DIM * INNER];
__device__ __half g_wff1[FFDIM * DIM];
__device__ __half g_wff2[DIM * FFDIM];

// --------------------------- async-copy helpers -----------------------------
__device__ __forceinline__ void cp16(uint32_t smem, const void* gmem) {
    asm volatile("cp.async.cg.shared.global [%0], [%1], 16;\n"
                 :: "r"(smem), "l"(gmem));
}
__device__ __forceinline__ void cp_commit() {
    asm volatile("cp.async.commit_group;\n" ::);
}
template<int N> __device__ __forceinline__ void cp_wait() {
    asm volatile("cp.async.wait_group %0;\n" :: "n"(N));
}
__device__ __forceinline__ uint32_t smem_u32(const void* p) {
    return (uint32_t)__cvta_generic_to_shared(p);
}

// --------------------------- numeric helpers --------------------------------
__device__ __forceinline__ uint32_t f2tf32(float f) {
    uint32_t r;
    asm("cvt.rna.tf32.f32 %0, %1;\n" : "=r"(r) : "f"(f));
    return r;
}
__device__ __forceinline__ float round_tf32(float f) {
    return __uint_as_float(f2tf32(f));
}
// fp16 mma: D(f32) += A(f16) * B(f16), m16n8k16
__device__ __forceinline__ void mma_f16(
    float& c0, float& c1, float& c2, float& c3,
    uint32_t a0, uint32_t a1, uint32_t a2, uint32_t a3,
    uint32_t b0, uint32_t b1)
{
    asm volatile(
        "mma.sync.aligned.m16n8k16.row.col.f32.f16.f16.f32 "
        "{%0,%1,%2,%3}, {%4,%5,%6,%7}, {%8,%9}, {%0,%1,%2,%3};\n"
        : "+f"(c0), "+f"(c1), "+f"(c2), "+f"(c3)
        : "r"(a0), "r"(a1), "r"(a2), "r"(a3), "r"(b0), "r"(b1));
}
// tf32 mma (for P*V)
__device__ __forceinline__ void mma_tf32(
    float& c0, float& c1, float& c2, float& c3,
    uint32_t a0, uint32_t a1, uint32_t a2, uint32_t a3,
    uint32_t b0, uint32_t b1)
{
    asm volatile(
        "mma.sync.aligned.m16n8k8.row.col.f32.tf32.tf32.f32 "
        "{%0,%1,%2,%3}, {%4,%5,%6,%7}, {%8,%9}, {%0,%1,%2,%3};\n"
        : "+f"(c0), "+f"(c1), "+f"(c2), "+f"(c3)
        : "r"(a0), "r"(a1), "r"(a2), "r"(a3), "r"(b0), "r"(b1));
}

// ----------------- weight transpose + fp16 convert (prep) -------------------
// in: [K, N] fp32 row-major -> out: [N, K] fp16 row-major.
__global__ __launch_bounds__(256) void transpose_h_kernel(
    const float* __restrict__ in, __half* __restrict__ out, int K, int N)
{
    __shared__ float t[32][33];
    const int n0 = blockIdx.x * 32, k0 = blockIdx.y * 32;
    const int tx = threadIdx.x & 31, ty = threadIdx.x >> 5;   // 32 x 8
    #pragma unroll
    for (int i = 0; i < 4; i++)
        t[ty + 8 * i][tx] = in[(size_t)(k0 + ty + 8 * i) * N + n0 + tx];
    __syncthreads();
    #pragma unroll
    for (int i = 0; i < 4; i++)
        out[(size_t)(n0 + ty + 8 * i) * K + k0 + tx] =
            __float2half_rn(t[tx][ty + 8 * i]);
}

// ------------------------------ LayerNorm (fp16 out) ------------------------
__global__ __launch_bounds__(256) void layernorm_kernel(
    const float* __restrict__ x, const float* __restrict__ g,
    const float* __restrict__ b, __half* __restrict__ y)
{
    __shared__ float red[2][8];
    const int row = blockIdx.x;
    const int tid = threadIdx.x;
    const float4* xr = reinterpret_cast<const float4*>(x + (size_t)row * DIM);
    float4 v = xr[tid];
    float s  = v.x + v.y + v.z + v.w;
    float ss = v.x * v.x + v.y * v.y + v.z * v.z + v.w * v.w;
    #pragma unroll
    for (int o = 16; o > 0; o >>= 1) {
        s  += __shfl_down_sync(0xffffffffu, s,  o);
        ss += __shfl_down_sync(0xffffffffu, ss, o);
    }
    if ((tid & 31) == 0) { red[0][tid >> 5] = s; red[1][tid >> 5] = ss; }
    __syncthreads();
    if (tid < 32) {
        s  = (tid < 8) ? red[0][tid] : 0.f;
        ss = (tid < 8) ? red[1][tid] : 0.f;
        #pragma unroll
        for (int o = 4; o > 0; o >>= 1) {
            s  += __shfl_down_sync(0xffffffffu, s,  o);
            ss += __shfl_down_sync(0xffffffffu, ss, o);
        }
        if (tid == 0) { red[0][0] = s; red[1][0] = ss; }
    }
    __syncthreads();
    const float mu  = red[0][0] * (1.f / DIM);
    const float var = red[1][0] * (1.f / DIM) - mu * mu;
    const float inv = rsqrtf(var + LN_EPS);
    const float4 gg = reinterpret_cast<const float4*>(g)[tid];
    const float4 bb = reinterpret_cast<const float4*>(b)[tid];
    __half2* yp = reinterpret_cast<__half2*>(y + (size_t)row * DIM + tid * 4);
    yp[0] = __floats2half2_rn((v.x - mu) * inv * gg.x + bb.x,
                              (v.y - mu) * inv * gg.y + bb.y);
    yp[1] = __floats2half2_rn((v.z - mu) * inv * gg.z + bb.z,
                              (v.w - mu) * inv * gg.w + bb.w);
}

// --------------------------- fp16 tensor GEMM -------------------------------
// C[M,N] = A[M,K] @ Wt[N,K]^T (+epilogue). CTA 128x128, BK=64 halfs, 8 warps,
// warp tile 64x32 (4mi x 4ni of 16x8 mma), 3-stage cp.async, 1 sync/iter.
// smem: [row][72 halfs] pad -> frag LDS bank = (4*g8+tig) mod 32, distinct.
#define E_QKV  0   // cols<2048 -> g_qk half; cols>=2048 -> g_v float (tf32 rnd)
#define E_GELU 1   // half(gelu(acc+bias))
#define E_RES  2   // fp32 acc + bias + res

#define HBK 64
#define HLD 72                               // halfs per row (144 B)
#define HTILE (128 * HLD)                    // halfs per operand tile
#define HSTAGES 3
#define GEMM_SMEM_BYTES ((HSTAGES * 2 * HTILE) * (int)sizeof(__half))

template<int EPI>
__global__ __launch_bounds__(256) void gemm_h_kernel(
    const __half* __restrict__ A, const __half* __restrict__ B,
    const float* __restrict__ bias, const float* __restrict__ res,
    void* __restrict__ C0, void* __restrict__ C1, int M, int N, int K)
{
    extern __shared__ __half smh[];
    __half* As = smh;                         // HSTAGES x HTILE
    __half* Bs = smh + HSTAGES * HTILE;       // HSTAGES x HTILE

    const int tid   = threadIdx.x;
    const int warp  = tid >> 5;
    const int lane  = tid & 31;
    const int warpM = warp >> 2;
    const int warpN = warp & 3;
    const int g8    = lane >> 2;
    const int tig   = lane & 3;

    const __half* Ab = A + (size_t)blockIdx.y * 128 * K;
    const __half* Bb = B + (size_t)blockIdx.x * 128 * K;

    float acc[4][4][4];
    #pragma unroll
    for (int mi = 0; mi < 4; mi++)
        #pragma unroll
        for (int ni = 0; ni < 4; ni++)
            #pragma unroll
            for (int q = 0; q < 4; q++) acc[mi][ni][q] = 0.f;

    auto issueTile = [&](int kt, int s) {
        __half* As_ = As + s * HTILE;
        __half* Bs_ = Bs + s * HTILE;
        #pragma unroll
        for (int i = 0; i < 4; i++) {               // A: 128 rows x 8 chunks
            int idx = tid + i * 256;                // 0..1023
            int r = idx >> 3, c = idx & 7;
            cp16(smem_u32(As_ + r * HLD + c * 8),
                 Ab + (size_t)r * K + kt * HBK + c * 8);
        }
        #pragma unroll
        for (int i = 0; i < 4; i++) {               // B: same shape
            int idx = tid + i * 256;
            int r = idx >> 3, c = idx & 7;
            cp16(smem_u32(Bs_ + r * HLD + c * 8),
                 Bb + (size_t)r * K + kt * HBK + c * 8);
        }
        cp_commit();
    };

    const int nk = K / HBK;                   // 16 (K=1024) or 64 (K=4096)
    issueTile(0, 0);
    issueTile(1, 1);

    for (int kt = 0; kt < nk; kt++) {
        const int cur = kt % HSTAGES;
        if (kt + 1 < nk) cp_wait<1>(); else cp_wait<0>();
        __syncthreads();
        if (kt + 2 < nk) issueTile(kt + 2, (kt + 2) % HSTAGES);

        const __half* As_ = As + cur * HTILE;
        const __half* Bs_ = Bs + cur * HTILE;

        #pragma unroll
        for (int kk = 0; kk < 4; kk++) {            // 4 x k16 per BK=64
            const int k0 = kk * 16 + tig * 2;
            uint32_t Af[4][4], Bf[4][2];
            #pragma unroll
            for (int mi = 0; mi < 4; mi++) {
                const int row0 = warpM * 64 + mi * 16 + g8;
                Af[mi][0] = *reinterpret_cast<const uint32_t*>(&As_[row0 * HLD + k0]);
                Af[mi][1] = *reinterpret_cast<const uint32_t*>(&As_[(row0 + 8) * HLD + k0]);
                Af[mi][2] = *reinterpret_cast<const uint32_t*>(&As_[row0 * HLD + k0 + 8]);
                Af[mi][3] = *reinterpret_cast<const uint32_t*>(&As_[(row0 + 8) * HLD + k0 + 8]);
            }
            #pragma unroll
            for (int ni = 0; ni < 4; ni++) {
                const int col = warpN * 32 + ni * 8 + g8;
                Bf[ni][0] = *reinterpret_cast<const uint32_t*>(&Bs_[col * HLD + k0]);
                Bf[ni][1] = *reinterpret_cast<const uint32_t*>(&Bs_[col * HLD + k0 + 8]);
            }
            #pragma unroll
            for (int mi = 0; mi < 4; mi++)
                #pragma unroll
                for (int ni = 0; ni < 4; ni++)
                    mma_f16(acc[mi][ni][0], acc[mi][ni][1],
                            acc[mi][ni][2], acc[mi][ni][3],
                            Af[mi][0], Af[mi][1], Af[mi][2], Af[mi][3],
                            Bf[ni][0], Bf[ni][1]);
        }
    }

    // ------------------------------ epilogue --------------------------------
    const int rbase = blockIdx.y * 128 + warpM * 64;
    const int cbase = blockIdx.x * 128;
    #pragma unroll
    for (int mi = 0; mi < 4; mi++) {
        #pragma unroll
        for (int ni = 0; ni < 4; ni++) {
            const int col0 = cbase + warpN * 32 + ni * 8 + tig * 2;
            #pragma unroll
            for (int half_ = 0; half_ < 2; half_++) {
                const int row = rbase + mi * 16 + g8 + half_ * 8;
                float v0 = acc[mi][ni][half_ * 2 + 0];
                float v1 = acc[mi][ni][half_ * 2 + 1];
                if (EPI == E_QKV) {
                    if (cbase < 2 * INNER) {        // Q|K -> half
                        __half2 hv = __floats2half2_rn(v0, v1);
                        *reinterpret_cast<__half2*>(
                            (__half*)C0 + (size_t)row * (2 * INNER) + col0) = hv;
                    } else {                        // V -> float (tf32-rounded)
                        *reinterpret_cast<float2*>(
                            (float*)C1 + (size_t)row * INNER + (col0 - 2 * INNER)) =
                            make_float2(round_tf32(v0), round_tf32(v1));
                    }
                } else if (EPI == E_GELU) {
                    v0 += bias[col0];
                    v1 += bias[col0 + 1];
                    v0 = 0.5f * v0 * (1.0f + erff(v0 * 0.70710678118654752f));
                    v1 = 0.5f * v1 * (1.0f + erff(v1 * 0.70710678118654752f));
                    __half2 hv = __floats2half2_rn(v0, v1);
                    *reinterpret_cast<__half2*>(
                        (__half*)C0 + (size_t)row * N + col0) = hv;
                } else {  // E_RES
                    const float2 rr = *reinterpret_cast<const float2*>(
                        res + (size_t)row * N + col0);
                    v0 += bias[col0]     + rr.x;
                    v1 += bias[col0 + 1] + rr.y;
                    *reinterpret_cast<float2*>(
                        (float*)C0 + (size_t)row * N + col0) = make_float2(v0, v1);
                }
            }
        }
    }
}

// ----------------------- flash attention (fp16 QK, tf32 PV) -----------------
#define KLDH 72                 // K smem stride in halfs (144 B)
#define VLD  72                 // V smem stride in floats
#define PLD  36                 // P smem stride in floats
#define KSZH (32 * KLDH)        // halfs
#define VSZ  (32 * VLD)         // floats
#define ASTAGES 3
#define ATTN_SMEM_BYTES (ASTAGES * (KSZH * 2 + VSZ * 4) + 128 * PLD * 4)

__global__ __launch_bounds__(128, 2) void flash_attn_kernel(
    const __half* __restrict__ qk, const float* __restrict__ vsrc,
    __half* __restrict__ out)
{
    constexpr int TK = 32, LD2 = 2 * INNER;
    extern __shared__ char smc[];
    __half* Ks = reinterpret_cast<__half*>(smc);                 // ASTAGES*KSZH
    float*  Vs = reinterpret_cast<float*>(smc + ASTAGES * KSZH * 2);
    float*  Ps = Vs + ASTAGES * VSZ;

    const int bh   = blockIdx.y;
    const int b    = bh / HEADS, h = bh % HEADS;
    const int tid  = threadIdx.x;
    const int warp = tid >> 5;
    const int lane = tid & 31;
    const int g8   = lane >> 2;
    const int tig  = lane & 3;

    const __half* qbase = qk + (size_t)b * SEQ * LD2;            // Q cols 0..1023
    const __half* kbase = qbase + INNER;                          // K cols 1024..
    const float*  vbase = vsrc + (size_t)b * SEQ * INNER;
    const int wq = blockIdx.x * 128 + warp * 32;

    // preload Q fp16 fragments: 4 k16-chunks over dh=64
    uint32_t Aq[2][4][4];
    #pragma unroll
    for (int mi = 0; mi < 2; mi++) {
        const int r0 = wq + mi * 16 + g8;
        const __half* q0 = qbase + (size_t)r0 * LD2 + h * DHEAD;
        const __half* q1 = q0 + 8 * LD2;
        #pragma unroll
        for (int kk = 0; kk < 4; kk++) {
            Aq[mi][kk][0] = *reinterpret_cast<const uint32_t*>(q0 + kk * 16 + tig * 2);
            Aq[mi][kk][1] = *reinterpret_cast<const uint32_t*>(q1 + kk * 16 + tig * 2);
            Aq[mi][kk][2] = *reinterpret_cast<const uint32_t*>(q0 + kk * 16 + tig * 2 + 8);
            Aq[mi][kk][3] = *reinterpret_cast<const uint32_t*>(q1 + kk * 16 + tig * 2 + 8);
        }
    }

    float accO[2][8][4];
    #pragma unroll
    for (int mi = 0; mi < 2; mi++)
        #pragma unroll
        for (int nd = 0; nd < 8; nd++)
            #pragma unroll
            for (int q = 0; q < 4; q++) accO[mi][nd][q] = 0.f;
    float mrow[2][2], lrow[2][2];
    #pragma unroll
    for (int mi = 0; mi < 2; mi++)
        #pragma unroll
        for (int hh = 0; hh < 2; hh++) { mrow[mi][hh] = -INFINITY; lrow[mi][hh] = 0.f; }

    const float scale = 0.125f;
    float* Pw = Ps + warp * 32 * PLD;

    auto issueKV = [&](int kt, int s) {
        __half* Ks_ = Ks + s * KSZH;
        float*  Vs_ = Vs + s * VSZ;
        // K: 32 rows x 64 halfs = 256 x 16B chunks -> 2 per thread
        #pragma unroll
        for (int i = 0; i < 2; i++) {
            int idx = tid + i * 128;          // 0..255
            int r = idx >> 3, c = idx & 7;
            const int srow = kt * TK + r;
            cp16(smem_u32(Ks_ + r * KLDH + c * 8),
                 kbase + (size_t)srow * LD2 + h * DHEAD + c * 8);
        }
        // V: 32 rows x 64 floats = 512 x 16B chunks -> 4 per thread
        #pragma unroll
        for (int i = 0; i < 4; i++) {
            int idx = tid + i * 128;          // 0..511
            int r = idx >> 4, c = idx & 15;
            const int srow = kt * TK + r;
            cp16(smem_u32(Vs_ + r * VLD + c * 4),
                 vbase + (size_t)srow * INNER + h * DHEAD + c * 4);
        }
        cp_commit();
    };

    const int nkt = SEQ / TK;
    issueKV(0, 0);
    issueKV(1, 1);

    for (int kt = 0; kt < nkt; kt++) {
        const int cur = kt % ASTAGES;
        if (kt + 1 < nkt) cp_wait<1>(); else cp_wait<0>();
        __syncthreads();
        if (kt + 2 < nkt) issueKV(kt + 2, (kt + 2) % ASTAGES);

        const __half* Ks_ = Ks + cur * KSZH;
        const float*  Vs_ = Vs + cur * VSZ;

        // ---- S = Q K^T  (fp16 mma, 4 k16 steps) ----
        float accS[2][4][4];
        #pragma unroll
        for (int mi = 0; mi < 2; mi++)
            #pragma unroll
            for (int ni = 0; ni < 4; ni++)
                #pragma unroll
                for (int q = 0; q < 4; q++) accS[mi][ni][q] = 0.f;

        #pragma unroll
        for (int kk = 0; kk < 4; kk++) {
            const int k0 = kk * 16 + tig * 2;
            uint32_t Bk[4][2];
            #pragma unroll
            for (int ni = 0; ni < 4; ni++) {
                const int key = ni * 8 + g8;
                Bk[ni][0] = *reinterpret_cast<const uint32_t*>(&Ks_[key * KLDH + k0]);
                Bk[ni][1] = *reinterpret_cast<const uint32_t*>(&Ks_[key * KLDH + k0 + 8]);
            }
            #pragma unroll
            for (int mi = 0; mi < 2; mi++)
                #pragma unroll
                for (int ni = 0; ni < 4; ni++)
                    mma_f16(accS[mi][ni][0], accS[mi][ni][1],
                            accS[mi][ni][2], accS[mi][ni][3],
                            Aq[mi][kk][0], Aq[mi][kk][1],
                            Aq[mi][kk][2], Aq[mi][kk][3],
                            Bk[ni][0], Bk[ni][1]);
        }

        // ---- online softmax + P (tf32-rounded at store) ----
        #pragma unroll
        for (int mi = 0; mi < 2; mi++) {
            #pragma unroll
            for (int hh = 0; hh < 2; hh++) {
                float v[8];
                #pragma unroll
                for (int ni = 0; ni < 4; ni++) {
                    v[ni * 2 + 0] = accS[mi][ni][hh * 2 + 0] * scale;
                    v[ni * 2 + 1] = accS[mi][ni][hh * 2 + 1] * scale;
                }
                float mx = v[0];
                #pragma unroll
                for (int j = 1; j < 8; j++) mx = fmaxf(mx, v[j]);
                mx = fmaxf(mx, __shfl_xor_sync(0xffffffffu, mx, 1));
                mx = fmaxf(mx, __shfl_xor_sync(0xffffffffu, mx, 2));

                const float mold = mrow[mi][hh];
                const float mnew = fmaxf(mold, mx);
                const float corr = __expf(mold - mnew);
                mrow[mi][hh] = mnew;

                float ps = 0.f;
                #pragma unroll
                for (int j = 0; j < 8; j++) {
                    v[j] = round_tf32(__expf(v[j] - mnew));
                    ps += v[j];
                }
                ps += __shfl_xor_sync(0xffffffffu, ps, 1);
                ps += __shfl_xor_sync(0xffffffffu, ps, 2);
                lrow[mi][hh] = lrow[mi][hh] * corr + ps;

                #pragma unroll
                for (int nd = 0; nd < 8; nd++) {
                    accO[mi][nd][hh * 2 + 0] *= corr;
                    accO[mi][nd][hh * 2 + 1] *= corr;
                }
                const int prow = mi * 16 + g8 + hh * 8;
                #pragma unroll
                for (int ni = 0; ni < 4; ni++)
                    *reinterpret_cast<float2*>(&Pw[prow * PLD + ni * 8 + tig * 2]) =
                        make_float2(v[ni * 2 + 0], v[ni * 2 + 1]);
            }
        }
        __syncwarp();

        // ---- O += P V  (tf32 mma, V tf32-rounded at source) ----
        #pragma unroll
        for (int kk = 0; kk < 4; kk++) {
            uint32_t Ap[2][4];
            #pragma unroll
            for (int mi = 0; mi < 2; mi++) {
                const int r0 = mi * 16 + g8;
                Ap[mi][0] = __float_as_uint(Pw[r0 * PLD + kk * 8 + tig]);
                Ap[mi][1] = __float_as_uint(Pw[(r0 + 8) * PLD + kk * 8 + tig]);
                Ap[mi][2] = __float_as_uint(Pw[r0 * PLD + kk * 8 + tig + 4]);
                Ap[mi][3] = __float_as_uint(Pw[(r0 + 8) * PLD + kk * 8 + tig + 4]);
            }
            #pragma unroll
            for (int nd = 0; nd < 8; nd++) {
                uint32_t b0 = __float_as_uint(Vs_[(kk * 8 + tig) * VLD + nd * 8 + g8]);
                uint32_t b1 = __float_as_uint(Vs_[(kk * 8 + tig + 4) * VLD + nd * 8 + g8]);
                #pragma unroll
                for (int mi = 0; mi < 2; mi++)
                    mma_tf32(accO[mi][nd][0], accO[mi][nd][1],
                             accO[mi][nd][2], accO[mi][nd][3],
                             Ap[mi][0], Ap[mi][1], Ap[mi][2], Ap[mi][3],
                             b0, b1);
            }
        }
        __syncwarp();
    }

    // ---- normalize + write out (fp16; consumed as GEMM A) ----
    #pragma unroll
    for (int mi = 0; mi < 2; mi++) {
        #pragma unroll
        for (int hh = 0; hh < 2; hh++) {
            const float inv = 1.f / lrow[mi][hh];
            const int row = wq + mi * 16 + g8 + hh * 8;
            __half* op = out + (size_t)(b * SEQ + row) * INNER + h * DHEAD;
            #pragma unroll
            for (int nd = 0; nd < 8; nd++) {
                __half2 hv = __floats2half2_rn(accO[mi][nd][hh * 2 + 0] * inv,
                                               accO[mi][nd][hh * 2 + 1] * inv);
                *reinterpret_cast<__half2*>(op + nd * 8 + tig * 2) = hv;
            }
        }
    }
}

// ------------------------------- launch -------------------------------------
extern "C" void kernel_launch(void* const* d_in, const int* in_sizes, int n_in,
                              void* d_out, int out_size)
{
    const float* x     = (const float*)d_in[0];
    const float* w_qkv = (const float*)d_in[1];
    const float* w_out = (const float*)d_in[2];
    const float* b_out = (const float*)d_in[3];
    const float* g1    = (const float*)d_in[4];
    const float* be1   = (const float*)d_in[5];
    const float* g2    = (const float*)d_in[6];
    const float* be2   = (const float*)d_in[7];
    const float* w_ff1 = (const float*)d_in[8];
    const float* b_ff1 = (const float*)d_in[9];
    const float* w_ff2 = (const float*)d_in[10];
    const float* b_ff2 = (const float*)d_in[11];
    float* out = (float*)d_out;

    __half *h, *qkh, *attn, *ff, *wq, *wo, *w1, *w2;
    float *v, *x1;
    cudaGetSymbolAddress((void**)&h,    g_h);
    cudaGetSymbolAddress((void**)&qkh,  g_qk);
    cudaGetSymbolAddress((void**)&v,    g_v);
    cudaGetSymbolAddress((void**)&attn, g_attn);
    cudaGetSymbolAddress((void**)&x1,   g_x1);
    cudaGetSymbolAddress((void**)&ff,   g_ff);
    cudaGetSymbolAddress((void**)&wq,   g_wqkv);
    cudaGetSymbolAddress((void**)&wo,   g_wout);
    cudaGetSymbolAddress((void**)&w1,   g_wff1);
    cudaGetSymbolAddress((void**)&w2,   g_wff2);

    cudaFuncSetAttribute(gemm_h_kernel<E_QKV>,
        cudaFuncAttributeMaxDynamicSharedMemorySize, GEMM_SMEM_BYTES);
    cudaFuncSetAttribute(gemm_h_kernel<E_GELU>,
        cudaFuncAttributeMaxDynamicSharedMemorySize, GEMM_SMEM_BYTES);
    cudaFuncSetAttribute(gemm_h_kernel<E_RES>,
        cudaFuncAttributeMaxDynamicSharedMemorySize, GEMM_SMEM_BYTES);
    cudaFuncSetAttribute(flash_attn_kernel,
        cudaFuncAttributeMaxDynamicSharedMemorySize, ATTN_SMEM_BYTES);

    // 0) transpose + fp16-convert all weights: Wt[N][K]
    transpose_h_kernel<<<dim3(3 * INNER / 32, DIM / 32), 256>>>(
        w_qkv, wq, DIM, 3 * INNER);
    transpose_h_kernel<<<dim3(DIM / 32, INNER / 32), 256>>>(
        w_out, wo, INNER, DIM);
    transpose_h_kernel<<<dim3(FFDIM / 32, DIM / 32), 256>>>(
        w_ff1, w1, DIM, FFDIM);
    transpose_h_kernel<<<dim3(DIM / 32, FFDIM / 32), 256>>>(
        w_ff2, w2, FFDIM, DIM);

    // 1) h = fp16(LN(x))
    layernorm_kernel<<<ROWS, 256>>>(x, g1, be1, h);
    // 2) qkv = h @ w_qkv  (Q,K -> fp16 g_qk; V -> fp32 tf32-rounded g_v)
    gemm_h_kernel<E_QKV><<<dim3(3 * INNER / 128, ROWS / 128), 256,
                           GEMM_SMEM_BYTES>>>(
        h, wq, nullptr, nullptr, qkh, v, ROWS, 3 * INNER, DIM);
    // 3) attn = fp16(MHA(qk, v))
    flash_attn_kernel<<<dim3(SEQ / 128, BATCH * HEADS), 128,
                        ATTN_SMEM_BYTES>>>(qkh, v, attn);
    // 4) x1 = x + attn @ w_out + b_out  (fp32)
    gemm_h_kernel<E_RES><<<dim3(DIM / 128, ROWS / 128), 256,
                           GEMM_SMEM_BYTES>>>(
        attn, wo, b_out, x, x1, nullptr, ROWS, DIM, INNER);
    // 5) h = fp16(LN(x1))
    layernorm_kernel<<<ROWS, 256>>>(x1, g2, be2, h);
    // 6) ff = fp16(gelu(h @ w_ff1 + b_ff1))
    gemm_h_kernel<E_GELU><<<dim3(FFDIM / 128, ROWS / 128), 256,
                            GEMM_SMEM_BYTES>>>(
        h, w1, b_ff1, nullptr, ff, nullptr, ROWS, FFDIM, DIM);
    // 7) out = x1 + ff @ w_ff2 + b_ff2  (fp32)
    gemm_h_kernel<E_RES><<<dim3(DIM / 128, ROWS / 128), 256,
                           GEMM_SMEM_BYTES>>>(
        ff, w2, b_ff2, x1, out, nullptr, ROWS, DIM, FFDIM);
}

// round 17
// speedup vs baseline: 1.6835x; 1.1007x over previous
#include <cuda_runtime.h>
#include <cuda_fp16.h>
#include <math.h>
#include <stdint.h>

// ---------------------------------------------------------------------------
// SimpleTransformerLayer on GB300 — Round 17
//   fp16 mma m16n8k16 GEMMs (unchanged, tensor-bound) + attention upgrades:
//   fp16 P*V via ldmatrix.x4.trans, conditional accO rescale, softmax scale
//   folded into K (exact 2^-3). 3-stage cp.async everywhere.
// ---------------------------------------------------------------------------

#define BATCH   2
#define SEQ     2048
#define DIM     1024
#define HEADS   16
#define DHEAD   64
#define INNER   1024
#define FFDIM   4096
#define ROWS    (BATCH * SEQ)
#define LN_EPS  1e-5f

__device__ __half g_h   [ROWS * DIM];         // LN output (fp16)
__device__ __half g_qk  [ROWS * 2 * INNER];   // Q|K of QKV (fp16; K pre-scaled by 1/8)
__device__ __half g_v   [ROWS * INNER];       // V part (fp16)
__device__ __half g_attn[ROWS * INNER];       // attention out (fp16)
__device__ float  g_x1  [ROWS * DIM];         // residual stream (fp32)
__device__ __half g_ff  [ROWS * FFDIM];       // GELU out (fp16)
// transposed fp16 weights: Wt[N][K]
__device__ __half g_wqkv[3 * INNER * DIM];
__device__ __half g_wout[DIM * INNER];
__device__ __half g_wff1[FFDIM * DIM];
__device__ __half g_wff2[DIM * FFDIM];

// --------------------------- async-copy helpers -----------------------------
__device__ __forceinline__ void cp16(uint32_t smem, const void* gmem) {
    asm volatile("cp.async.cg.shared.global [%0], [%1], 16;\n"
                 :: "r"(smem), "l"(gmem));
}
__device__ __forceinline__ void cp_commit() {
    asm volatile("cp.async.commit_group;\n" ::);
}
template<int N> __device__ __forceinline__ void cp_wait() {
    asm volatile("cp.async.wait_group %0;\n" :: "n"(N));
}
__device__ __forceinline__ uint32_t smem_u32(const void* p) {
    return (uint32_t)__cvta_generic_to_shared(p);
}

// --------------------------- mma / ldmatrix helpers -------------------------
__device__ __forceinline__ void mma_f16(
    float& c0, float& c1, float& c2, float& c3,
    uint32_t a0, uint32_t a1, uint32_t a2, uint32_t a3,
    uint32_t b0, uint32_t b1)
{
    asm volatile(
        "mma.sync.aligned.m16n8k16.row.col.f32.f16.f16.f32 "
        "{%0,%1,%2,%3}, {%4,%5,%6,%7}, {%8,%9}, {%0,%1,%2,%3};\n"
        : "+f"(c0), "+f"(c1), "+f"(c2), "+f"(c3)
        : "r"(a0), "r"(a1), "r"(a2), "r"(a3), "r"(b0), "r"(b1));
}
__device__ __forceinline__ void ldsm_x4_t(
    uint32_t& r0, uint32_t& r1, uint32_t& r2, uint32_t& r3, uint32_t addr)
{
    asm volatile(
        "ldmatrix.sync.aligned.m8n8.x4.trans.shared.b16 {%0,%1,%2,%3}, [%4];\n"
        : "=r"(r0), "=r"(r1), "=r"(r2), "=r"(r3) : "r"(addr));
}

// ----------------- weight transpose + fp16 convert (prep) -------------------
__global__ __launch_bounds__(256) void transpose_h_kernel(
    const float* __restrict__ in, __half* __restrict__ out, int K, int N)
{
    __shared__ float t[32][33];
    const int n0 = blockIdx.x * 32, k0 = blockIdx.y * 32;
    const int tx = threadIdx.x & 31, ty = threadIdx.x >> 5;
    #pragma unroll
    for (int i = 0; i < 4; i++)
        t[ty + 8 * i][tx] = in[(size_t)(k0 + ty + 8 * i) * N + n0 + tx];
    __syncthreads();
    #pragma unroll
    for (int i = 0; i < 4; i++)
        out[(size_t)(n0 + ty + 8 * i) * K + k0 + tx] =
            __float2half_rn(t[tx][ty + 8 * i]);
}

// ------------------------------ LayerNorm (fp16 out) ------------------------
__global__ __launch_bounds__(256) void layernorm_kernel(
    const float* __restrict__ x, const float* __restrict__ g,
    const float* __restrict__ b, __half* __restrict__ y)
{
    __shared__ float red[2][8];
    const int row = blockIdx.x;
    const int tid = threadIdx.x;
    const float4* xr = reinterpret_cast<const float4*>(x + (size_t)row * DIM);
    float4 v = xr[tid];
    float s  = v.x + v.y + v.z + v.w;
    float ss = v.x * v.x + v.y * v.y + v.z * v.z + v.w * v.w;
    #pragma unroll
    for (int o = 16; o > 0; o >>= 1) {
        s  += __shfl_down_sync(0xffffffffu, s,  o);
        ss += __shfl_down_sync(0xffffffffu, ss, o);
    }
    if ((tid & 31) == 0) { red[0][tid >> 5] = s; red[1][tid >> 5] = ss; }
    __syncthreads();
    if (tid < 32) {
        s  = (tid < 8) ? red[0][tid] : 0.f;
        ss = (tid < 8) ? red[1][tid] : 0.f;
        #pragma unroll
        for (int o = 4; o > 0; o >>= 1) {
            s  += __shfl_down_sync(0xffffffffu, s,  o);
            ss += __shfl_down_sync(0xffffffffu, ss, o);
        }
        if (tid == 0) { red[0][0] = s; red[1][0] = ss; }
    }
    __syncthreads();
    const float mu  = red[0][0] * (1.f / DIM);
    const float var = red[1][0] * (1.f / DIM) - mu * mu;
    const float inv = rsqrtf(var + LN_EPS);
    const float4 gg = reinterpret_cast<const float4*>(g)[tid];
    const float4 bb = reinterpret_cast<const float4*>(b)[tid];
    __half2* yp = reinterpret_cast<__half2*>(y + (size_t)row * DIM + tid * 4);
    yp[0] = __floats2half2_rn((v.x - mu) * inv * gg.x + bb.x,
                              (v.y - mu) * inv * gg.y + bb.y);
    yp[1] = __floats2half2_rn((v.z - mu) * inv * gg.z + bb.z,
                              (v.w - mu) * inv * gg.w + bb.w);
}

// --------------------------- fp16 tensor GEMM -------------------------------
// Identical structure to round 16 (tensor-bound). E_QKV now writes K scaled by
// 1/8 (exact) and V as fp16.
#define E_QKV  0
#define E_GELU 1
#define E_RES  2

#define HBK 64
#define HLD 72
#define HTILE (128 * HLD)
#define HSTAGES 3
#define GEMM_SMEM_BYTES ((HSTAGES * 2 * HTILE) * (int)sizeof(__half))

template<int EPI>
__global__ __launch_bounds__(256) void gemm_h_kernel(
    const __half* __restrict__ A, const __half* __restrict__ B,
    const float* __restrict__ bias, const float* __restrict__ res,
    void* __restrict__ C0, void* __restrict__ C1, int M, int N, int K)
{
    extern __shared__ __half smh[];
    __half* As = smh;
    __half* Bs = smh + HSTAGES * HTILE;

    const int tid   = threadIdx.x;
    const int warp  = tid >> 5;
    const int lane  = tid & 31;
    const int warpM = warp >> 2;
    const int warpN = warp & 3;
    const int g8    = lane >> 2;
    const int tig   = lane & 3;

    const __half* Ab = A + (size_t)blockIdx.y * 128 * K;
    const __half* Bb = B + (size_t)blockIdx.x * 128 * K;

    float acc[4][4][4];
    #pragma unroll
    for (int mi = 0; mi < 4; mi++)
        #pragma unroll
        for (int ni = 0; ni < 4; ni++)
            #pragma unroll
            for (int q = 0; q < 4; q++) acc[mi][ni][q] = 0.f;

    auto issueTile = [&](int kt, int s) {
        __half* As_ = As + s * HTILE;
        __half* Bs_ = Bs + s * HTILE;
        #pragma unroll
        for (int i = 0; i < 4; i++) {
            int idx = tid + i * 256;
            int r = idx >> 3, c = idx & 7;
            cp16(smem_u32(As_ + r * HLD + c * 8),
                 Ab + (size_t)r * K + kt * HBK + c * 8);
        }
        #pragma unroll
        for (int i = 0; i < 4; i++) {
            int idx = tid + i * 256;
            int r = idx >> 3, c = idx & 7;
            cp16(smem_u32(Bs_ + r * HLD + c * 8),
                 Bb + (size_t)r * K + kt * HBK + c * 8);
        }
        cp_commit();
    };

    const int nk = K / HBK;
    issueTile(0, 0);
    issueTile(1, 1);

    for (int kt = 0; kt < nk; kt++) {
        const int cur = kt % HSTAGES;
        if (kt + 1 < nk) cp_wait<1>(); else cp_wait<0>();
        __syncthreads();
        if (kt + 2 < nk) issueTile(kt + 2, (kt + 2) % HSTAGES);

        const __half* As_ = As + cur * HTILE;
        const __half* Bs_ = Bs + cur * HTILE;

        #pragma unroll
        for (int kk = 0; kk < 4; kk++) {
            const int k0 = kk * 16 + tig * 2;
            uint32_t Af[4][4], Bf[4][2];
            #pragma unroll
            for (int mi = 0; mi < 4; mi++) {
                const int row0 = warpM * 64 + mi * 16 + g8;
                Af[mi][0] = *reinterpret_cast<const uint32_t*>(&As_[row0 * HLD + k0]);
                Af[mi][1] = *reinterpret_cast<const uint32_t*>(&As_[(row0 + 8) * HLD + k0]);
                Af[mi][2] = *reinterpret_cast<const uint32_t*>(&As_[row0 * HLD + k0 + 8]);
                Af[mi][3] = *reinterpret_cast<const uint32_t*>(&As_[(row0 + 8) * HLD + k0 + 8]);
            }
            #pragma unroll
            for (int ni = 0; ni < 4; ni++) {
                const int col = warpN * 32 + ni * 8 + g8;
                Bf[ni][0] = *reinterpret_cast<const uint32_t*>(&Bs_[col * HLD + k0]);
                Bf[ni][1] = *reinterpret_cast<const uint32_t*>(&Bs_[col * HLD + k0 + 8]);
            }
            #pragma unroll
            for (int mi = 0; mi < 4; mi++)
                #pragma unroll
                for (int ni = 0; ni < 4; ni++)
                    mma_f16(acc[mi][ni][0], acc[mi][ni][1],
                            acc[mi][ni][2], acc[mi][ni][3],
                            Af[mi][0], Af[mi][1], Af[mi][2], Af[mi][3],
                            Bf[ni][0], Bf[ni][1]);
        }
    }

    // ------------------------------ epilogue --------------------------------
    const int rbase = blockIdx.y * 128 + warpM * 64;
    const int cbase = blockIdx.x * 128;
    #pragma unroll
    for (int mi = 0; mi < 4; mi++) {
        #pragma unroll
        for (int ni = 0; ni < 4; ni++) {
            const int col0 = cbase + warpN * 32 + ni * 8 + tig * 2;
            #pragma unroll
            for (int half_ = 0; half_ < 2; half_++) {
                const int row = rbase + mi * 16 + g8 + half_ * 8;
                float v0 = acc[mi][ni][half_ * 2 + 0];
                float v1 = acc[mi][ni][half_ * 2 + 1];
                if (EPI == E_QKV) {
                    if (cbase < 2 * INNER) {        // Q|K -> half
                        if (cbase >= INNER) {       // K: fold softmax scale (2^-3, exact)
                            v0 *= 0.125f;
                            v1 *= 0.125f;
                        }
                        __half2 hv = __floats2half2_rn(v0, v1);
                        *reinterpret_cast<__half2*>(
                            (__half*)C0 + (size_t)row * (2 * INNER) + col0) = hv;
                    } else {                        // V -> fp16
                        __half2 hv = __floats2half2_rn(v0, v1);
                        *reinterpret_cast<__half2*>(
                            (__half*)C1 + (size_t)row * INNER + (col0 - 2 * INNER)) = hv;
                    }
                } else if (EPI == E_GELU) {
                    v0 += bias[col0];
                    v1 += bias[col0 + 1];
                    v0 = 0.5f * v0 * (1.0f + erff(v0 * 0.70710678118654752f));
                    v1 = 0.5f * v1 * (1.0f + erff(v1 * 0.70710678118654752f));
                    __half2 hv = __floats2half2_rn(v0, v1);
                    *reinterpret_cast<__half2*>(
                        (__half*)C0 + (size_t)row * N + col0) = hv;
                } else {  // E_RES
                    const float2 rr = *reinterpret_cast<const float2*>(
                        res + (size_t)row * N + col0);
                    v0 += bias[col0]     + rr.x;
                    v1 += bias[col0 + 1] + rr.y;
                    *reinterpret_cast<float2*>(
                        (float*)C0 + (size_t)row * N + col0) = make_float2(v0, v1);
                }
            }
        }
    }
}

// -------------------- flash attention (all-fp16 mma) ------------------------
// S = Q K^T fp16 (K pre-scaled); softmax with conditional rescale; P fp16;
// O += P V via fp16 mma with V B-frags from ldmatrix.x4.trans.
#define KLDH 72                 // K smem stride (halfs, 144 B)
#define VLDH 72                 // V smem stride (halfs, 144 B)
#define PLDH 40                 // P smem stride (halfs, 80 B)
#define KSZH (32 * KLDH)
#define VSZH (32 * VLDH)
#define ASTAGES 3
#define ATTN_SMEM_BYTES ((ASTAGES * (KSZH + VSZH) + 128 * PLDH) * (int)sizeof(__half))

__global__ __launch_bounds__(128, 2) void flash_attn_kernel(
    const __half* __restrict__ qk, const __half* __restrict__ vsrc,
    __half* __restrict__ out)
{
    constexpr int TK = 32, LD2 = 2 * INNER;
    extern __shared__ __half smh[];
    __half* Ks = smh;                                  // ASTAGES x KSZH
    __half* Vs = smh + ASTAGES * KSZH;                 // ASTAGES x VSZH
    __half* Ps = smh + ASTAGES * (KSZH + VSZH);        // 128 x PLDH

    const int bh   = blockIdx.y;
    const int b    = bh / HEADS, h = bh % HEADS;
    const int tid  = threadIdx.x;
    const int warp = tid >> 5;
    const int lane = tid & 31;
    const int g8   = lane >> 2;
    const int tig  = lane & 3;

    const __half* qbase = qk + (size_t)b * SEQ * LD2;  // Q cols 0..1023
    const __half* kbase = qbase + INNER;                // K cols 1024.. (pre-scaled)
    const __half* vbase = vsrc + (size_t)b * SEQ * INNER;
    const int wq = blockIdx.x * 128 + warp * 32;

    // preload Q fp16 fragments: 4 k16-chunks over dh=64
    uint32_t Aq[2][4][4];
    #pragma unroll
    for (int mi = 0; mi < 2; mi++) {
        const int r0 = wq + mi * 16 + g8;
        const __half* q0 = qbase + (size_t)r0 * LD2 + h * DHEAD;
        const __half* q1 = q0 + 8 * LD2;
        #pragma unroll
        for (int kk = 0; kk < 4; kk++) {
            Aq[mi][kk][0] = *reinterpret_cast<const uint32_t*>(q0 + kk * 16 + tig * 2);
            Aq[mi][kk][1] = *reinterpret_cast<const uint32_t*>(q1 + kk * 16 + tig * 2);
            Aq[mi][kk][2] = *reinterpret_cast<const uint32_t*>(q0 + kk * 16 + tig * 2 + 8);
            Aq[mi][kk][3] = *reinterpret_cast<const uint32_t*>(q1 + kk * 16 + tig * 2 + 8);
        }
    }

    float accO[2][8][4];
    #pragma unroll
    for (int mi = 0; mi < 2; mi++)
        #pragma unroll
        for (int nd = 0; nd < 8; nd++)
            #pragma unroll
            for (int q = 0; q < 4; q++) accO[mi][nd][q] = 0.f;
    float mrow[2][2], lrow[2][2];
    #pragma unroll
    for (int mi = 0; mi < 2; mi++)
        #pragma unroll
        for (int hh = 0; hh < 2; hh++) { mrow[mi][hh] = -INFINITY; lrow[mi][hh] = 0.f; }

    __half* Pw = Ps + warp * 32 * PLDH;

    auto issueKV = [&](int kt, int s) {
        __half* Ks_ = Ks + s * KSZH;
        __half* Vs_ = Vs + s * VSZH;
        // K: 32 rows x 64 halfs = 256 x 16B chunks -> 2 per thread
        #pragma unroll
        for (int i = 0; i < 2; i++) {
            int idx = tid + i * 128;
            int r = idx >> 3, c = idx & 7;
            const int srow = kt * TK + r;
            cp16(smem_u32(Ks_ + r * KLDH + c * 8),
                 kbase + (size_t)srow * LD2 + h * DHEAD + c * 8);
        }
        // V: same shape, fp16
        #pragma unroll
        for (int i = 0; i < 2; i++) {
            int idx = tid + i * 128;
            int r = idx >> 3, c = idx & 7;
            const int srow = kt * TK + r;
            cp16(smem_u32(Vs_ + r * VLDH + c * 8),
                 vbase + (size_t)srow * INNER + h * DHEAD + c * 8);
        }
        cp_commit();
    };

    const int nkt = SEQ / TK;
    issueKV(0, 0);
    issueKV(1, 1);

    for (int kt = 0; kt < nkt; kt++) {
        const int cur = kt % ASTAGES;
        if (kt + 1 < nkt) cp_wait<1>(); else cp_wait<0>();
        __syncthreads();
        if (kt + 2 < nkt) issueKV(kt + 2, (kt + 2) % ASTAGES);

        const __half* Ks_ = Ks + cur * KSZH;
        const __half* Vs_ = Vs + cur * VSZH;

        // ---- S = Q K^T (fp16 mma; scale already folded into K) ----
        float accS[2][4][4];
        #pragma unroll
        for (int mi = 0; mi < 2; mi++)
            #pragma unroll
            for (int ni = 0; ni < 4; ni++)
                #pragma unroll
                for (int q = 0; q < 4; q++) accS[mi][ni][q] = 0.f;

        #pragma unroll
        for (int kk = 0; kk < 4; kk++) {
            const int k0 = kk * 16 + tig * 2;
            uint32_t Bk[4][2];
            #pragma unroll
            for (int ni = 0; ni < 4; ni++) {
                const int key = ni * 8 + g8;
                Bk[ni][0] = *reinterpret_cast<const uint32_t*>(&Ks_[key * KLDH + k0]);
                Bk[ni][1] = *reinterpret_cast<const uint32_t*>(&Ks_[key * KLDH + k0 + 8]);
            }
            #pragma unroll
            for (int mi = 0; mi < 2; mi++)
                #pragma unroll
                for (int ni = 0; ni < 4; ni++)
                    mma_f16(accS[mi][ni][0], accS[mi][ni][1],
                            accS[mi][ni][2], accS[mi][ni][3],
                            Aq[mi][kk][0], Aq[mi][kk][1],
                            Aq[mi][kk][2], Aq[mi][kk][3],
                            Bk[ni][0], Bk[ni][1]);
        }

        // ---- online softmax: conditional rescale + fp16 P ----
        #pragma unroll
        for (int mi = 0; mi < 2; mi++) {
            #pragma unroll
            for (int hh = 0; hh < 2; hh++) {
                float v[8];
                #pragma unroll
                for (int ni = 0; ni < 4; ni++) {
                    v[ni * 2 + 0] = accS[mi][ni][hh * 2 + 0];
                    v[ni * 2 + 1] = accS[mi][ni][hh * 2 + 1];
                }
                float mx = v[0];
                #pragma unroll
                for (int j = 1; j < 8; j++) mx = fmaxf(mx, v[j]);
                mx = fmaxf(mx, __shfl_xor_sync(0xffffffffu, mx, 1));
                mx = fmaxf(mx, __shfl_xor_sync(0xffffffffu, mx, 2));

                const float mold = mrow[mi][hh];
                if (mx > mold) {                    // quad-uniform branch
                    const float corr = __expf(mold - mx);
                    mrow[mi][hh] = mx;
                    lrow[mi][hh] *= corr;
                    #pragma unroll
                    for (int nd = 0; nd < 8; nd++) {
                        accO[mi][nd][hh * 2 + 0] *= corr;
                        accO[mi][nd][hh * 2 + 1] *= corr;
                    }
                }
                const float mcur = mrow[mi][hh];
                const int prow = mi * 16 + g8 + hh * 8;
                float ps = 0.f;
                #pragma unroll
                for (int ni = 0; ni < 4; ni++) {
                    const float e0 = __expf(v[ni * 2 + 0] - mcur);
                    const float e1 = __expf(v[ni * 2 + 1] - mcur);
                    const __half2 hp = __floats2half2_rn(e0, e1);
                    const float2 bk = __half22float2(hp);   // l sums rounded P
                    ps += bk.x + bk.y;
                    *reinterpret_cast<__half2*>(
                        &Pw[prow * PLDH + ni * 8 + tig * 2]) = hp;
                }
                ps += __shfl_xor_sync(0xffffffffu, ps, 1);
                ps += __shfl_xor_sync(0xffffffffu, ps, 2);
                lrow[mi][hh] += ps;
            }
        }
        __syncwarp();

        // ---- O += P V  (fp16 mma; V B-frags via ldmatrix.x4.trans) ----
        #pragma unroll
        for (int kk = 0; kk < 2; kk++) {            // 2 x k16 over 32 keys
            uint32_t Ap[2][4];
            #pragma unroll
            for (int mi = 0; mi < 2; mi++) {
                const int r0  = mi * 16 + g8;
                const int kof = kk * 16 + tig * 2;
                Ap[mi][0] = *reinterpret_cast<const uint32_t*>(&Pw[r0 * PLDH + kof]);
                Ap[mi][1] = *reinterpret_cast<const uint32_t*>(&Pw[(r0 + 8) * PLDH + kof]);
                Ap[mi][2] = *reinterpret_cast<const uint32_t*>(&Pw[r0 * PLDH + kof + 8]);
                Ap[mi][3] = *reinterpret_cast<const uint32_t*>(&Pw[(r0 + 8) * PLDH + kof + 8]);
            }
            const int vrow = kk * 16 + (lane & 15);
            #pragma unroll
            for (int ndp = 0; ndp < 4; ndp++) {     // each covers nd = 2ndp, 2ndp+1
                const int vcol = ndp * 16 + (lane >> 4) * 8;
                uint32_t b0, b1, b2, b3;
                ldsm_x4_t(b0, b1, b2, b3,
                          smem_u32(Vs_ + vrow * VLDH + vcol));
                #pragma unroll
                for (int mi = 0; mi < 2; mi++) {
                    mma_f16(accO[mi][2 * ndp][0],     accO[mi][2 * ndp][1],
                            accO[mi][2 * ndp][2],     accO[mi][2 * ndp][3],
                            Ap[mi][0], Ap[mi][1], Ap[mi][2], Ap[mi][3], b0, b1);
                    mma_f16(accO[mi][2 * ndp + 1][0], accO[mi][2 * ndp + 1][1],
                            accO[mi][2 * ndp + 1][2], accO[mi][2 * ndp + 1][3],
                            Ap[mi][0], Ap[mi][1], Ap[mi][2], Ap[mi][3], b2, b3);
                }
            }
        }
        __syncwarp();
    }

    // ---- normalize + write out (fp16; consumed as GEMM A) ----
    #pragma unroll
    for (int mi = 0; mi < 2; mi++) {
        #pragma unroll
        for (int hh = 0; hh < 2; hh++) {
            const float inv = 1.f / lrow[mi][hh];
            const int row = wq + mi * 16 + g8 + hh * 8;
            __half* op = out + (size_t)(b * SEQ + row) * INNER + h * DHEAD;
            #pragma unroll
            for (int nd = 0; nd < 8; nd++) {
                __half2 hv = __floats2half2_rn(accO[mi][nd][hh * 2 + 0] * inv,
                                               accO[mi][nd][hh * 2 + 1] * inv);
                *reinterpret_cast<__half2*>(op + nd * 8 + tig * 2) = hv;
            }
        }
    }
}

// ------------------------------- launch -------------------------------------
extern "C" void kernel_launch(void* const* d_in, const int* in_sizes, int n_in,
                              void* d_out, int out_size)
{
    const float* x     = (const float*)d_in[0];
    const float* w_qkv = (const float*)d_in[1];
    const float* w_out = (const float*)d_in[2];
    const float* b_out = (const float*)d_in[3];
    const float* g1    = (const float*)d_in[4];
    const float* be1   = (const float*)d_in[5];
    const float* g2    = (const float*)d_in[6];
    const float* be2   = (const float*)d_in[7];
    const float* w_ff1 = (const float*)d_in[8];
    const float* b_ff1 = (const float*)d_in[9];
    const float* w_ff2 = (const float*)d_in[10];
    const float* b_ff2 = (const float*)d_in[11];
    float* out = (float*)d_out;

    __half *h, *qkh, *v, *attn, *ff, *wq, *wo, *w1, *w2;
    float *x1;
    cudaGetSymbolAddress((void**)&h,    g_h);
    cudaGetSymbolAddress((void**)&qkh,  g_qk);
    cudaGetSymbolAddress((void**)&v,    g_v);
    cudaGetSymbolAddress((void**)&attn, g_attn);
    cudaGetSymbolAddress((void**)&x1,   g_x1);
    cudaGetSymbolAddress((void**)&ff,   g_ff);
    cudaGetSymbolAddress((void**)&wq,   g_wqkv);
    cudaGetSymbolAddress((void**)&wo,   g_wout);
    cudaGetSymbolAddress((void**)&w1,   g_wff1);
    cudaGetSymbolAddress((void**)&w2,   g_wff2);

    cudaFuncSetAttribute(gemm_h_kernel<E_QKV>,
        cudaFuncAttributeMaxDynamicSharedMemorySize, GEMM_SMEM_BYTES);
    cudaFuncSetAttribute(gemm_h_kernel<E_GELU>,
        cudaFuncAttributeMaxDynamicSharedMemorySize, GEMM_SMEM_BYTES);
    cudaFuncSetAttribute(gemm_h_kernel<E_RES>,
        cudaFuncAttributeMaxDynamicSharedMemorySize, GEMM_SMEM_BYTES);
    cudaFuncSetAttribute(flash_attn_kernel,
        cudaFuncAttributeMaxDynamicSharedMemorySize, ATTN_SMEM_BYTES);

    // 0) transpose + fp16-convert all weights: Wt[N][K]
    transpose_h_kernel<<<dim3(3 * INNER / 32, DIM / 32), 256>>>(
        w_qkv, wq, DIM, 3 * INNER);
    transpose_h_kernel<<<dim3(DIM / 32, INNER / 32), 256>>>(
        w_out, wo, INNER, DIM);
    transpose_h_kernel<<<dim3(FFDIM / 32, DIM / 32), 256>>>(
        w_ff1, w1, DIM, FFDIM);
    transpose_h_kernel<<<dim3(DIM / 32, FFDIM / 32), 256>>>(
        w_ff2, w2, FFDIM, DIM);

    // 1) h = fp16(LN(x))
    layernorm_kernel<<<ROWS, 256>>>(x, g1, be1, h);
    // 2) qkv = h @ w_qkv  (Q -> fp16; K -> fp16 * 1/8; V -> fp16)
    gemm_h_kernel<E_QKV><<<dim3(3 * INNER / 128, ROWS / 128), 256,
                           GEMM_SMEM_BYTES>>>(
        h, wq, nullptr, nullptr, qkh, v, ROWS, 3 * INNER, DIM);
    // 3) attn = fp16(MHA(qk, v))
    flash_attn_kernel<<<dim3(SEQ / 128, BATCH * HEADS), 128,
                        ATTN_SMEM_BYTES>>>(qkh, v, attn);
    // 4) x1 = x + attn @ w_out + b_out  (fp32)
    gemm_h_kernel<E_RES><<<dim3(DIM / 128, ROWS / 128), 256,
                           GEMM_SMEM_BYTES>>>(
        attn, wo, b_out, x, x1, nullptr, ROWS, DIM, INNER);
    // 5) h = fp16(LN(x1))
    layernorm_kernel<<<ROWS, 256>>>(x1, g2, be2, h);
    // 6) ff = fp16(gelu(h @ w_ff1 + b_ff1))
    gemm_h_kernel<E_GELU><<<dim3(FFDIM / 128, ROWS / 128), 256,
                            GEMM_SMEM_BYTES>>>(
        h, w1, b_ff1, nullptr, ff, nullptr, ROWS, FFDIM, DIM);
    // 7) out = x1 + ff @ w_ff2 + b_ff2  (fp32)
    gemm_h_kernel<E_RES><<<dim3(DIM / 128, ROWS / 128), 256,
                           GEMM_SMEM_BYTES>>>(
        ff, w2, b_ff2, x1, out, nullptr, ROWS, DIM, FFDIM);
}